// round 6
// baseline (speedup 1.0000x reference)
#include <cuda_runtime.h>
#include <cuda_bf16.h>

// Problem constants
#define NVEC   65536      // N = B*H*W = 16*64*64
#define KCODE  1024
#define DIM    64
#define HW     4096       // H*W
#define CHW    262144     // C*H*W
#define NB     16

// Output layout (concatenated in reference return order, all fp32)
#define QUANT_OFF 0
#define LOSS_OFF  4194304
#define PERP_OFF  4194305
#define NCS_OFF   4194306
#define EMAW_OFF  4195330
#define EMBW_OFF  4260866

#define NTILES   1024     // 64-row work tiles
#define GRID_ARG 592      // 148 SMs * 4 blocks

// Scratch (device globals — no allocation allowed)
__device__ int   g_idx[NVEC];
__device__ __align__(16) float g_Wt[DIM * KCODE];     // Wt[d][k]
__device__ float g_w2[KCODE];
__device__ int   g_counts[KCODE];
__device__ __align__(16) float g_dw[KCODE * DIM];
__device__ __align__(16) float g_embed[KCODE * DIM];  // aligned copy of new codebook
__device__ float g_loss;
__device__ int   g_tile;

// ---------------------------------------------------------------------------
// Kernel A: prep — transpose W, ||w||^2, zero accumulators, reset tile counter
// ---------------------------------------------------------------------------
__global__ void prep_kernel(const float* __restrict__ W) {
    int i = blockIdx.x * 256 + threadIdx.x;   // 0..65535
    g_dw[i] = 0.f;
    int d = i >> 10;
    int k = i & 1023;
    g_Wt[i] = W[k * DIM + d];
    if (i < KCODE) {
        g_counts[i] = 0;
        const float* row = W + i * DIM;
        float s = 0.f;
        #pragma unroll
        for (int dd = 0; dd < DIM; ++dd) {
            float v = row[dd];
            s = fmaf(v, v, s);
        }
        g_w2[i] = s;
    }
    if (i == 0) { g_loss = 0.f; g_tile = 0; }
}

// ---------------------------------------------------------------------------
// Kernel B: persistent fused distance-GEMM + argmin + counts + dw scatter.
// 128 threads. Work tile: 64 rows. Code tiles: 16 x 64 codes, cp.async
// double-buffered (latency fully hidden). Thread tile: 4 rows x 8 codes.
// ws rows are chunk-permuted (float4 chunk j -> slot (j>>1)+((j&1)<<3)) so
// both b-operand LDS.128 are bank-conflict-free; a-reads are broadcasts.
// Smem: xs 16K + ws(2x16K)/red union 32K = 0xC000 exactly; tile index is
// bounced through xs[0][0].
// ---------------------------------------------------------------------------
__global__ void __launch_bounds__(128) argmin_kernel(const float* __restrict__ in) {
    __shared__ __align__(16) float xs[DIM][64];          // 16 KB, xs[d][row]
    __shared__ union USm {
        float ws[2][DIM][64];                            // 2x16 KB, permuted rows
        struct { float rv[64][8]; int ri[64][8]; } red;  // 4 KB overlay
    } u;

    const int tid = threadIdx.x;     // 0..127
    const int tx  = tid & 7;         // code group (8 x 8 codes)
    const int ty  = tid >> 3;        // row group  (16 x 4 rows)

    for (;;) {
        if (tid == 0)
            *reinterpret_cast<volatile int*>(&xs[0][0]) = atomicAdd(&g_tile, 1);
        __syncthreads();
        const int tile = *reinterpret_cast<volatile int*>(&xs[0][0]);
        __syncthreads();              // all threads read tile before xs overwrite
        if (tile >= NTILES) return;

        const int n0  = tile * 64;
        const int b   = n0 >> 12;        // 4096 rows per image
        const int hw0 = n0 & 4095;

        // --- prefetch ws code-tile 0 into buffer 0 (cp.async, 8 x 16B/thread)
        {
            #pragma unroll
            for (int i = 0; i < 8; ++i) {
                int c = i * 128 + tid;             // chunk id over 64d x 16 chunks
                int d = c >> 4;
                int j = c & 15;
                int slot = (j >> 1) + ((j & 1) << 3);
                unsigned dst = (unsigned)__cvta_generic_to_shared(&u.ws[0][d][slot * 4]);
                const float* src = g_Wt + d * KCODE + j * 4;
                asm volatile("cp.async.cg.shared.global [%0], [%1], 16;\n"
                             :: "r"(dst), "l"(src));
            }
            asm volatile("cp.async.commit_group;\n" ::: "memory");
        }

        // --- load x tile: xs[d][c] = in[b*CHW + d*HW + hw0 + c], coalesced
        const float* src = in + (size_t)b * CHW + hw0;
        #pragma unroll
        for (int i = 0; i < 8; ++i) {
            int fidx = i * 128 + tid;          // float4 index over 64x16
            int d  = fidx >> 4;
            int c4 = fidx & 15;
            float4 v = __ldg(reinterpret_cast<const float4*>(src + d * HW + c4 * 4));
            *reinterpret_cast<float4*>(&xs[d][c4 * 4]) = v;
        }

        float minv[4];
        int   mink[4];
        #pragma unroll
        for (int r = 0; r < 4; ++r) { minv[r] = 3.4e38f; mink[r] = 0; }

        for (int t16 = 0; t16 < 16; ++t16) {
            const int cur = t16 & 1;
            __syncthreads();   // all warps done with buffer 'cur^1' (and xs ready at t16=0)

            // prefetch next code tile into the other buffer
            if (t16 + 1 < 16) {
                const float* base = g_Wt + (t16 + 1) * 64;
                #pragma unroll
                for (int i = 0; i < 8; ++i) {
                    int c = i * 128 + tid;
                    int d = c >> 4;
                    int j = c & 15;
                    int slot = (j >> 1) + ((j & 1) << 3);
                    unsigned dst = (unsigned)__cvta_generic_to_shared(
                                       &u.ws[cur ^ 1][d][slot * 4]);
                    const float* sp = base + d * KCODE + j * 4;
                    asm volatile("cp.async.cg.shared.global [%0], [%1], 16;\n"
                                 :: "r"(dst), "l"(sp));
                }
            }
            asm volatile("cp.async.commit_group;\n" ::: "memory");

            // wait for current tile's data (1 group may stay in flight)
            if (t16 == 15)
                asm volatile("cp.async.wait_group 0;\n" ::: "memory");
            else
                asm volatile("cp.async.wait_group 1;\n" ::: "memory");
            __syncthreads();   // current buffer fully populated for all warps

            float acc[4][8];
            #pragma unroll
            for (int r = 0; r < 4; ++r)
                #pragma unroll
                for (int j = 0; j < 8; ++j) acc[r][j] = 0.f;

            #pragma unroll 4
            for (int d = 0; d < DIM; ++d) {
                float4 a  = *reinterpret_cast<const float4*>(&xs[d][ty * 4]);
                float4 b0 = *reinterpret_cast<const float4*>(&u.ws[cur][d][tx * 4]);
                float4 b1 = *reinterpret_cast<const float4*>(&u.ws[cur][d][tx * 4 + 32]);
                float ar[4] = {a.x, a.y, a.z, a.w};
                float br[8] = {b0.x, b0.y, b0.z, b0.w, b1.x, b1.y, b1.z, b1.w};
                #pragma unroll
                for (int r = 0; r < 4; ++r)
                    #pragma unroll
                    for (int j = 0; j < 8; ++j)
                        acc[r][j] = fmaf(ar[r], br[j], acc[r][j]);
            }

            // epilogue: dist = w2 - 2*dot (x^2 per-row constant, argmin-invariant)
            #pragma unroll
            for (int j = 0; j < 8; ++j) {
                int kg = t16 * 64 + tx * 8 + j;
                float w2v = __ldg(&g_w2[kg]);
                #pragma unroll
                for (int r = 0; r < 4; ++r) {
                    float v = fmaf(-2.f, acc[r][j], w2v);
                    if (v < minv[r]) { minv[r] = v; mink[r] = kg; }
                }
            }
        }

        __syncthreads();   // all done with ws before red overlay

        // --- cross-thread reduction (8 candidates per row)
        #pragma unroll
        for (int r = 0; r < 4; ++r) {
            int row = ty * 4 + r;
            u.red.rv[row][tx] = minv[r];
            u.red.ri[row][tx] = mink[r];
        }
        __syncthreads();

        if (tid < 64) {
            float bv = u.red.rv[tid][0];
            int   bi = u.red.ri[tid][0];
            #pragma unroll
            for (int t = 1; t < 8; ++t) {
                float v  = u.red.rv[tid][t];
                int   ii = u.red.ri[tid][t];
                if (v < bv || (v == bv && ii < bi)) { bv = v; bi = ii; }
            }
            g_idx[n0 + tid] = bi;
            atomicAdd(&g_counts[bi], 1);
            u.red.ri[tid][0] = bi;     // publish for dw scatter
        }
        __syncthreads();

        // --- dw scatter: dw[k][d] += x[n][d] (conflict-free smem reads)
        {
            int row   = tid & 63;
            int dbase = (tid >> 6) * 32;
            int kk = u.red.ri[row][0];
            float* dst = &g_dw[kk * DIM + dbase];
            #pragma unroll
            for (int i = 0; i < 32; ++i)
                atomicAdd(&dst[i], xs[dbase + i][row]);
        }
        __syncthreads();   // protect xs / red before next tile
    }
}

// ---------------------------------------------------------------------------
// Kernel C: codebook EMA update + perplexity (single block, 1024 threads)
// ---------------------------------------------------------------------------
__global__ void update_kernel(const float* __restrict__ ecs,
                              const float* __restrict__ emw,
                              float* __restrict__ out) {
    int k = threadIdx.x;
    __shared__ float sm[KCODE];

    float c   = (float)g_counts[k];
    float ncs = ecs[k] * 0.99f + 0.01f * c;
    out[NCS_OFF + k] = ncs;

    sm[k] = ncs; __syncthreads();
    for (int s = 512; s > 0; s >>= 1) {
        if (k < s) sm[k] += sm[k + s];
        __syncthreads();
    }
    float nsum = sm[0];
    __syncthreads();

    // perplexity
    float p = c * (1.f / (float)NVEC);
    sm[k] = p * logf(p + 1e-10f);
    __syncthreads();
    for (int s = 512; s > 0; s >>= 1) {
        if (k < s) sm[k] += sm[k + s];
        __syncthreads();
    }
    if (k == 0) out[PERP_OFF] = expf(-sm[0]);

    float normalized = (ncs + 1e-5f) / (nsum + 1024.f * 1e-5f) * nsum;
    float inv = 1.f / normalized;
    #pragma unroll
    for (int d = 0; d < DIM; ++d) {
        int i = k * DIM + d;
        float nw = emw[i] * 0.99f + 0.01f * g_dw[i];
        float e  = nw * inv;
        out[EMAW_OFF + i] = nw;
        out[EMBW_OFF + i] = e;
        g_embed[i] = e;            // aligned copy for float4 gathers in quant
    }
}

// ---------------------------------------------------------------------------
// Kernel D: quantize + loss. Each thread covers 4 consecutive d's per row so
// the codebook gather is one aligned float4 (from g_embed). grid = 1024.
// ---------------------------------------------------------------------------
__global__ void quant_kernel(const float* __restrict__ in,
                             float* __restrict__ out) {
    int blk = blockIdx.x;
    int b  = blk >> 6;
    int d0 = ((blk >> 2) & 15) * 4;
    int hc = blk & 3;
    int t  = threadIdx.x;

    const size_t pbase = (size_t)b * CHW + (size_t)d0 * HW;
    const int nbase = b * HW;

    float local = 0.f;
    #pragma unroll
    for (int it = 0; it < 4; ++it) {
        int hw = hc * 1024 + it * 256 + t;
        int kk = g_idx[nbase + hw];
        float4 q = *reinterpret_cast<const float4*>(&g_embed[kk * DIM + d0]);
        float qa[4] = {q.x, q.y, q.z, q.w};
        #pragma unroll
        for (int j = 0; j < 4; ++j) {
            size_t off = pbase + (size_t)j * HW + hw;
            float x = in[off];
            out[QUANT_OFF + off] = qa[j];   // x + (q - x) == q
            float diff = x - qa[j];
            local = fmaf(diff, diff, local);
        }
    }

    #pragma unroll
    for (int o = 16; o > 0; o >>= 1)
        local += __shfl_down_sync(0xffffffff, local, o);
    __shared__ float wsum[8];
    if ((t & 31) == 0) wsum[t >> 5] = local;
    __syncthreads();
    if (t == 0) {
        float s = 0.f;
        #pragma unroll
        for (int i = 0; i < 8; ++i) s += wsum[i];
        atomicAdd(&g_loss, s);
    }
}

// ---------------------------------------------------------------------------
// Kernel E: finalize loss
// ---------------------------------------------------------------------------
__global__ void loss_kernel(float* __restrict__ out) {
    out[LOSS_OFF] = 0.25f * g_loss * (1.f / (float)(NVEC * DIM));
}

extern "C" void kernel_launch(void* const* d_in, const int* in_sizes, int n_in,
                              void* d_out, int out_size) {
    const float* in  = (const float*)d_in[0];  // [16,64,64,64]
    const float* W   = (const float*)d_in[1];  // [1024,64]
    const float* ecs = (const float*)d_in[2];  // [1024]
    const float* emw = (const float*)d_in[3];  // [1024,64]
    float* out = (float*)d_out;

    prep_kernel<<<256, 256>>>(W);
    argmin_kernel<<<GRID_ARG, 128>>>(in);
    update_kernel<<<1, 1024>>>(ecs, emw, out);
    quant_kernel<<<1024, 256>>>(in, out);
    loss_kernel<<<1, 1>>>(out);
}